// round 3
// baseline (speedup 1.0000x reference)
#include <cuda_runtime.h>
#include <math.h>
#include <stdint.h>

#define B_  256
#define T_  512
#define D_  128
#define H_  256
#define G_  768
#define C_  10

#define NCTA_SCAN 128

// ---------------- scratch (device globals; no allocation allowed) ----------------
__device__ float g_gi[(size_t)B_ * T_ * G_];   // 100,663,296 floats (~403 MB), reused for both layers
__device__ float g_h1[(size_t)T_ * B_ * H_];   // layer-0 hidden states, [T][B][H]
__device__ float g_hbuf[2][B_ * H_];           // ping-pong hidden state
__device__ volatile unsigned g_bar_gen = 0;
__device__ unsigned g_bar_cnt = 0;

// ---------------- grid barrier (all NCTA_SCAN CTAs resident by construction) -----
__device__ __forceinline__ void gridbar()
{
    __threadfence();
    __syncthreads();
    if (threadIdx.x == 0) {
        unsigned g = g_bar_gen;
        unsigned a = atomicAdd(&g_bar_cnt, 1u);
        if (a == (unsigned)(NCTA_SCAN - 1)) {
            atomicExch(&g_bar_cnt, 0u);
            __threadfence();
            g_bar_gen = g + 1u;
        } else {
            while (g_bar_gen == g) { __nanosleep(32); }
        }
    }
    __syncthreads();
    __threadfence();
}

// ---------------- SGEMM: C[M,768] = A[M,K] @ W[768,K]^T + bias -------------------
// BM=128, BN=128, BK=16, 256 threads, 8x8 register tile, register prefetch.
__global__ void __launch_bounds__(256, 2) gemm_nt(
    const float* __restrict__ A, const float* __restrict__ W,
    const float* __restrict__ bias, float* __restrict__ C, int K)
{
    __shared__ float As[16][128];
    __shared__ float Ws[16][128];

    const int m0 = blockIdx.x * 128;
    const int n0 = blockIdx.y * 128;
    const int tid = threadIdx.x;
    const int tx = tid & 15;        // n-direction
    const int ty = tid >> 4;        // m-direction

    // tile load mapping: 512 float4 per operand tile, 2 per thread
    const int f0 = tid * 2, f1 = tid * 2 + 1;
    const int am0 = f0 >> 2, ak0 = (f0 & 3) * 4;
    const int am1 = f1 >> 2, ak1 = (f1 & 3) * 4;

    const float* Ap = A + (size_t)m0 * K;
    const float* Wp = W + (size_t)n0 * K;

    float4 pa0 = *(const float4*)(Ap + (size_t)am0 * K + ak0);
    float4 pa1 = *(const float4*)(Ap + (size_t)am1 * K + ak1);
    float4 pw0 = *(const float4*)(Wp + (size_t)am0 * K + ak0);
    float4 pw1 = *(const float4*)(Wp + (size_t)am1 * K + ak1);

    float acc[8][8];
#pragma unroll
    for (int i = 0; i < 8; i++)
#pragma unroll
        for (int j = 0; j < 8; j++) acc[i][j] = 0.f;

    const int nkt = K >> 4;
    for (int kb = 0; kb < nkt; kb++) {
        As[ak0 + 0][am0] = pa0.x; As[ak0 + 1][am0] = pa0.y;
        As[ak0 + 2][am0] = pa0.z; As[ak0 + 3][am0] = pa0.w;
        As[ak1 + 0][am1] = pa1.x; As[ak1 + 1][am1] = pa1.y;
        As[ak1 + 2][am1] = pa1.z; As[ak1 + 3][am1] = pa1.w;
        Ws[ak0 + 0][am0] = pw0.x; Ws[ak0 + 1][am0] = pw0.y;
        Ws[ak0 + 2][am0] = pw0.z; Ws[ak0 + 3][am0] = pw0.w;
        Ws[ak1 + 0][am1] = pw1.x; Ws[ak1 + 1][am1] = pw1.y;
        Ws[ak1 + 2][am1] = pw1.z; Ws[ak1 + 3][am1] = pw1.w;
        __syncthreads();

        if (kb + 1 < nkt) {
            const int ko = (kb + 1) * 16;
            pa0 = *(const float4*)(Ap + (size_t)am0 * K + ko + ak0);
            pa1 = *(const float4*)(Ap + (size_t)am1 * K + ko + ak1);
            pw0 = *(const float4*)(Wp + (size_t)am0 * K + ko + ak0);
            pw1 = *(const float4*)(Wp + (size_t)am1 * K + ko + ak1);
        }

#pragma unroll
        for (int k = 0; k < 16; k++) {
            float av[8], wv[8];
            *(float4*)&av[0] = *(const float4*)&As[k][ty * 4];
            *(float4*)&av[4] = *(const float4*)&As[k][64 + ty * 4];
            *(float4*)&wv[0] = *(const float4*)&Ws[k][tx * 4];
            *(float4*)&wv[4] = *(const float4*)&Ws[k][64 + tx * 4];
#pragma unroll
            for (int i = 0; i < 8; i++)
#pragma unroll
                for (int j = 0; j < 8; j++) acc[i][j] += av[i] * wv[j];
        }
        __syncthreads();
    }

    // epilogue: add bias, store float4
#pragma unroll
    for (int i = 0; i < 8; i++) {
        const int mrow = m0 + ty * 4 + (i & 3) + ((i >> 2) * 64);
        const int c0 = n0 + tx * 4;
        float4 o0, o1;
        o0.x = acc[i][0] + bias[c0 + 0];
        o0.y = acc[i][1] + bias[c0 + 1];
        o0.z = acc[i][2] + bias[c0 + 2];
        o0.w = acc[i][3] + bias[c0 + 3];
        o1.x = acc[i][4] + bias[c0 + 64 + 0];
        o1.y = acc[i][5] + bias[c0 + 64 + 1];
        o1.z = acc[i][6] + bias[c0 + 64 + 2];
        o1.w = acc[i][7] + bias[c0 + 64 + 3];
        *(float4*)&C[(size_t)mrow * G_ + c0]       = o0;
        *(float4*)&C[(size_t)mrow * G_ + c0 + 64]  = o1;
    }
}

// ---------------- zero hidden state ----------------------------------------------
__global__ void zero_h()
{
    int i = blockIdx.x * blockDim.x + threadIdx.x;
    if (i < B_ * H_) g_hbuf[0][i] = 0.f;
}

// ---------------- persistent GRU scan ---------------------------------------------
// grid = 128 CTAs x 256 threads. CTA (bblk, jblk): batch slice of 64, hidden slice of 8.
// Whh slice (24 rows x 256) lives in smem for all 512 steps. Warp-split-K over k,
// 8b x 6g register tiles per lane, smem tree-reduction, gate math, ping-pong h.
__global__ void __launch_bounds__(256, 1) gru_scan(
    const float* __restrict__ gi, const float* __restrict__ Whh,
    const float* __restrict__ bhh, float* __restrict__ hseq, int tmajor)
{
    extern __shared__ float sm[];
    float* wsl  = sm;                    // [24][257]
    float* bsl  = wsl + 24 * 257;        // [24]
    float* hs   = bsl + 24;              // [64][257]
    float* part = hs + 64 * 257;         // [8][64][24]
    float* gis  = part + 8 * 64 * 24;    // [64][24]
    float* hst  = gis + 64 * 24;         // [64][8]

    const int tid = threadIdx.x;
    const int c = blockIdx.x;
    const int b0 = (c >> 5) * 64;
    const int j0 = (c & 31) * 8;

    // persistent Whh slice: rows {j0..j0+7, H+j0.., 2H+j0..}
    for (int idx = tid; idx < 24 * 256; idx += 256) {
        const int row = idx >> 8, k = idx & 255;
        const int gate = row >> 3, jj = row & 7;
        wsl[row * 257 + k] = Whh[(size_t)(gate * H_ + j0 + jj) * H_ + k];
    }
    if (tid < 24) {
        const int gate = tid >> 3, jj = tid & 7;
        bsl[tid] = bhh[gate * H_ + j0 + jj];
    }

    const int w = tid >> 5, lane = tid & 31;
    const int kbase = w * 32;
    const int bl = lane & 7;             // lane's base batch row (interleaved -> conflict-free)
    const int g0l = (lane >> 3) * 6;     // lane's gate-column block

    for (int t = 0; t < T_; t++) {
        const float* hprev = g_hbuf[t & 1];
        float* hnext = g_hbuf[(t & 1) ^ 1];

        // stage h_prev slice (coalesced)
#pragma unroll 8
        for (int idx = tid; idx < 64 * 256; idx += 256) {
            const int b = idx >> 8, k = idx & 255;
            hs[b * 257 + k] = hprev[(b0 + b) * H_ + k];
        }
        // stage gi slice (64 b x 24 cols)
        for (int idx = tid; idx < 64 * 24; idx += 256) {
            const int b = idx / 24, gg = idx % 24;
            const int gate = gg >> 3, jj = gg & 7;
            const size_t row = tmajor ? ((size_t)t * B_ + b0 + b)
                                      : ((size_t)(b0 + b) * T_ + t);
            gis[idx] = gi[row * G_ + gate * H_ + j0 + jj];
        }
        __syncthreads();

        // warp-split-K partial GEMM: gh_partial[64][24] for k in [kbase, kbase+32)
        float acc[8][6];
#pragma unroll
        for (int i = 0; i < 8; i++)
#pragma unroll
            for (int g = 0; g < 6; g++) acc[i][g] = 0.f;

#pragma unroll 4
        for (int kk = 0; kk < 32; kk++) {
            const int k = kbase + kk;
            float wv[6];
#pragma unroll
            for (int g = 0; g < 6; g++) wv[g] = wsl[(g0l + g) * 257 + k];
#pragma unroll
            for (int i = 0; i < 8; i++) {
                const float hv = hs[(bl + 8 * i) * 257 + k];
#pragma unroll
                for (int g = 0; g < 6; g++) acc[i][g] += hv * wv[g];
            }
        }
#pragma unroll
        for (int i = 0; i < 8; i++) {
            const int b = bl + 8 * i;
#pragma unroll
            for (int g = 0; g < 6; g++)
                part[(w * 64 + b) * 24 + g0l + g] = acc[i][g];
        }
        __syncthreads();

        // reduce 8 partials + gates; each thread handles 2 (b, jj) pairs
#pragma unroll
        for (int p = 0; p < 2; p++) {
            const int pr = tid + p * 256;
            const int b = pr & 63, jj = pr >> 6;
            const int ccr = jj, ccz = 8 + jj, ccn = 16 + jj;
            float sr = bsl[ccr], sz = bsl[ccz], sn = bsl[ccn];
#pragma unroll
            for (int ww = 0; ww < 8; ww++) {
                const int base = (ww * 64 + b) * 24;
                sr += part[base + ccr];
                sz += part[base + ccz];
                sn += part[base + ccn];
            }
            sr += gis[b * 24 + ccr];
            sz += gis[b * 24 + ccz];
            const float r = 1.f / (1.f + expf(-sr));
            const float z = 1.f / (1.f + expf(-sz));
            const float n = tanhf(gis[b * 24 + ccn] + r * sn);
            const float hold = hs[b * 257 + j0 + jj];
            hst[b * 8 + jj] = (1.f - z) * n + z * hold;
        }
        __syncthreads();

        // coalesced writeback of h_new (and sequence output for layer 0)
        for (int idx = tid; idx < 512; idx += 256) {
            const int b = idx >> 3, jj = idx & 7;
            const float v = hst[idx];
            hnext[(b0 + b) * H_ + j0 + jj] = v;
            if (hseq) hseq[((size_t)t * B_ + b0 + b) * H_ + j0 + jj] = v;
        }
        gridbar();
    }
}

// ---------------- final FC: out[256,10] = h @ Wfc^T + bfc -------------------------
__global__ void fc_kernel(const float* __restrict__ h, const float* __restrict__ Wfc,
                          const float* __restrict__ bfc, float* __restrict__ out)
{
    const int b = blockIdx.x;
    const int lane = threadIdx.x;
    float hv[8];
#pragma unroll
    for (int i = 0; i < 8; i++) hv[i] = h[b * H_ + lane + 32 * i];
    for (int cc = 0; cc < C_; cc++) {
        float s = 0.f;
#pragma unroll
        for (int i = 0; i < 8; i++) s += hv[i] * Wfc[cc * H_ + lane + 32 * i];
#pragma unroll
        for (int o = 16; o > 0; o >>= 1) s += __shfl_down_sync(0xffffffffu, s, o);
        if (lane == 0) out[b * C_ + cc] = s + bfc[cc];
    }
}

// ---------------- launch ----------------------------------------------------------
extern "C" void kernel_launch(void* const* d_in, const int* in_sizes, int n_in,
                              void* d_out, int out_size)
{
    (void)in_sizes; (void)n_in; (void)out_size;
    const float* x    = (const float*)d_in[0];
    const float* Wih0 = (const float*)d_in[1];
    const float* Whh0 = (const float*)d_in[2];
    const float* bih0 = (const float*)d_in[3];
    const float* bhh0 = (const float*)d_in[4];
    const float* Wih1 = (const float*)d_in[5];
    const float* Whh1 = (const float*)d_in[6];
    const float* bih1 = (const float*)d_in[7];
    const float* bhh1 = (const float*)d_in[8];
    const float* Wfc  = (const float*)d_in[9];
    const float* bfc  = (const float*)d_in[10];
    float* out = (float*)d_out;

    float *p_gi, *p_h1, *p_hb;
    cudaGetSymbolAddress((void**)&p_gi, g_gi);
    cudaGetSymbolAddress((void**)&p_h1, g_h1);
    cudaGetSymbolAddress((void**)&p_hb, g_hbuf);

    const int scan_smem = (24 * 257 + 24 + 64 * 257 + 8 * 64 * 24 + 64 * 24 + 512) * 4;
    cudaFuncSetAttribute(gru_scan, cudaFuncAttributeMaxDynamicSharedMemorySize, scan_smem);

    const dim3 gg(1024, 6);  // M/128 = 131072/128, N/128 = 768/128

    // layer 0: gi0 = x @ Wih0^T + bih0   (gi layout [B][T][768])
    gemm_nt<<<gg, 256>>>(x, Wih0, bih0, p_gi, D_);
    zero_h<<<256, 256>>>();
    gru_scan<<<NCTA_SCAN, 256, scan_smem>>>(p_gi, Whh0, bhh0, p_h1, /*tmajor=*/0);

    // layer 1: gi1 = h1 @ Wih1^T + bih1  (h1 and gi1 in [T][B][*] layout)
    gemm_nt<<<gg, 256>>>(p_h1, Wih1, bih1, p_gi, H_);
    zero_h<<<256, 256>>>();
    gru_scan<<<NCTA_SCAN, 256, scan_smem>>>(p_gi, Whh1, bhh1, nullptr, /*tmajor=*/1);

    // classifier on final hidden state (lives in g_hbuf[0] after 512 steps)
    fc_kernel<<<B_, 32>>>(p_hb, Wfc, bfc, out);
}

// round 4
// speedup vs baseline: 1.7552x; 1.7552x over previous
#include <cuda_runtime.h>
#include <math.h>
#include <stdint.h>

#define B_  256
#define T_  512
#define D_  128
#define H_  256
#define G_  768
#define C_  10

#define NCTA_SCAN 128
#define GRP_CTAS  32

// ---------------- scratch (device globals; no allocation allowed) ----------------
__device__ float g_gi[(size_t)B_ * T_ * G_];   // gi for current layer (~403 MB)
__device__ float g_h1[(size_t)T_ * B_ * H_];   // layer-0 hidden states, [T][B][H]
__device__ float g_hbuf[2][B_ * H_];           // ping-pong hidden state
__device__ volatile unsigned g_gen[4 * 32];    // per-group barrier generation (padded lines)
__device__ unsigned g_cnt[4 * 32];             // per-group arrival counter

// ---------------- SGEMM: C[M,768] = A[M,K] @ W[768,K]^T + bias -------------------
// BM=128, BN=128, BK=16, 256 threads, 8x8 register tile, register prefetch.
__global__ void __launch_bounds__(256, 2) gemm_nt(
    const float* __restrict__ A, const float* __restrict__ W,
    const float* __restrict__ bias, float* __restrict__ C, int K)
{
    __shared__ float As[16][128];
    __shared__ float Ws[16][128];

    const int m0 = blockIdx.x * 128;
    const int n0 = blockIdx.y * 128;
    const int tid = threadIdx.x;
    const int tx = tid & 15;        // n-direction
    const int ty = tid >> 4;        // m-direction

    const int f0 = tid * 2, f1 = tid * 2 + 1;
    const int am0 = f0 >> 2, ak0 = (f0 & 3) * 4;
    const int am1 = f1 >> 2, ak1 = (f1 & 3) * 4;

    const float* Ap = A + (size_t)m0 * K;
    const float* Wp = W + (size_t)n0 * K;

    float4 pa0 = *(const float4*)(Ap + (size_t)am0 * K + ak0);
    float4 pa1 = *(const float4*)(Ap + (size_t)am1 * K + ak1);
    float4 pw0 = *(const float4*)(Wp + (size_t)am0 * K + ak0);
    float4 pw1 = *(const float4*)(Wp + (size_t)am1 * K + ak1);

    float acc[8][8];
#pragma unroll
    for (int i = 0; i < 8; i++)
#pragma unroll
        for (int j = 0; j < 8; j++) acc[i][j] = 0.f;

    const int nkt = K >> 4;
    for (int kb = 0; kb < nkt; kb++) {
        As[ak0 + 0][am0] = pa0.x; As[ak0 + 1][am0] = pa0.y;
        As[ak0 + 2][am0] = pa0.z; As[ak0 + 3][am0] = pa0.w;
        As[ak1 + 0][am1] = pa1.x; As[ak1 + 1][am1] = pa1.y;
        As[ak1 + 2][am1] = pa1.z; As[ak1 + 3][am1] = pa1.w;
        Ws[ak0 + 0][am0] = pw0.x; Ws[ak0 + 1][am0] = pw0.y;
        Ws[ak0 + 2][am0] = pw0.z; Ws[ak0 + 3][am0] = pw0.w;
        Ws[ak1 + 0][am1] = pw1.x; Ws[ak1 + 1][am1] = pw1.y;
        Ws[ak1 + 2][am1] = pw1.z; Ws[ak1 + 3][am1] = pw1.w;
        __syncthreads();

        if (kb + 1 < nkt) {
            const int ko = (kb + 1) * 16;
            pa0 = *(const float4*)(Ap + (size_t)am0 * K + ko + ak0);
            pa1 = *(const float4*)(Ap + (size_t)am1 * K + ko + ak1);
            pw0 = *(const float4*)(Wp + (size_t)am0 * K + ko + ak0);
            pw1 = *(const float4*)(Wp + (size_t)am1 * K + ko + ak1);
        }

#pragma unroll
        for (int k = 0; k < 16; k++) {
            float av[8], wv[8];
            *(float4*)&av[0] = *(const float4*)&As[k][ty * 4];
            *(float4*)&av[4] = *(const float4*)&As[k][64 + ty * 4];
            *(float4*)&wv[0] = *(const float4*)&Ws[k][tx * 4];
            *(float4*)&wv[4] = *(const float4*)&Ws[k][64 + tx * 4];
#pragma unroll
            for (int i = 0; i < 8; i++)
#pragma unroll
                for (int j = 0; j < 8; j++) acc[i][j] += av[i] * wv[j];
        }
        __syncthreads();
    }

#pragma unroll
    for (int i = 0; i < 8; i++) {
        const int mrow = m0 + ty * 4 + (i & 3) + ((i >> 2) * 64);
        const int c0 = n0 + tx * 4;
        float4 o0, o1;
        o0.x = acc[i][0] + bias[c0 + 0];
        o0.y = acc[i][1] + bias[c0 + 1];
        o0.z = acc[i][2] + bias[c0 + 2];
        o0.w = acc[i][3] + bias[c0 + 3];
        o1.x = acc[i][4] + bias[c0 + 64 + 0];
        o1.y = acc[i][5] + bias[c0 + 64 + 1];
        o1.z = acc[i][6] + bias[c0 + 64 + 2];
        o1.w = acc[i][7] + bias[c0 + 64 + 3];
        *(float4*)&C[(size_t)mrow * G_ + c0]       = o0;
        *(float4*)&C[(size_t)mrow * G_ + c0 + 64]  = o1;
    }
}

// ---------------- persistent GRU scan, v2 ------------------------------------------
// 128 CTAs x 256 threads. CTA (bblk 0..3, jblk 0..31): 64 batches x 8 hidden dims.
// Whh slice (24 x 256) persistent in smem. 8-warp split-K, 8b x 6g register tiles,
// float4 smem operand loads, conflict-free padded strides, per-group (32 CTA)
// grid barrier, gi prefetch double-buffered under the GEMM.
__global__ void __launch_bounds__(256, 1) gru_scan(
    const float* __restrict__ gi, const float* __restrict__ Whh,
    const float* __restrict__ bhh, float* __restrict__ hseq, int tmajor)
{
    extern __shared__ float sm[];
    float* wsl  = sm;                 // [24][260]   = 6240
    float* bsl  = sm + 6240;          // [24] pad 32
    float* hs   = sm + 6272;          // [64][260]   = 16640
    float* part = sm + 22912;         // [8][64][25] = 12800
    float* gis  = sm + 35712;         // [2][64*25]  = 3200
    float* hst  = sm + 38912;         // [64][9]     = 576   (total 39488 floats)

    const int tid = threadIdx.x;
    const int cta = blockIdx.x;
    const int b0  = (cta >> 5) * 64;
    const int j0  = (cta & 31) * 8;
    const int grp = (cta >> 5) * 32;  // padded barrier slot

    // persistent Whh slice: rows {j0..j0+7, H+j0.., 2H+j0..}
    for (int idx = tid; idx < 24 * 256; idx += 256) {
        const int row = idx >> 8, k = idx & 255;
        wsl[row * 260 + k] = Whh[(size_t)((row >> 3) * H_ + j0 + (row & 7)) * H_ + k];
    }
    if (tid < 24) bsl[tid] = bhh[(tid >> 3) * H_ + j0 + (tid & 7)];

    const int w    = tid >> 5, lane = tid & 31;
    const int kbase = w * 32;
    const int bl   = lane & 7;
    const int g0l  = (lane >> 3) * 6;

    // per-thread gi staging map (6 elements), fixed across steps
    int   gq_b[6], gq_sm[6];
    int   gq_col[6];
#pragma unroll
    for (int q = 0; q < 6; q++) {
        const int idx = tid + 256 * q;
        const int b = idx / 24, gg = idx % 24;
        gq_b[q] = b;
        gq_sm[q] = b * 25 + gg;
        gq_col[q] = (gg >> 3) * H_ + j0 + (gg & 7);
    }

    // prefetch gi(t=0) into buffer 0
    float greg[6];
#pragma unroll
    for (int q = 0; q < 6; q++) {
        const size_t row = tmajor ? ((size_t)0 * B_ + b0 + gq_b[q])
                                  : ((size_t)(b0 + gq_b[q]) * T_ + 0);
        greg[q] = gi[row * G_ + gq_col[q]];
    }
#pragma unroll
    for (int q = 0; q < 6; q++) gis[gq_sm[q]] = greg[q];
    __syncthreads();

    for (int t = 0; t < T_; t++) {
        const float* hprev = g_hbuf[t & 1];
        float* hnext = g_hbuf[(t & 1) ^ 1];
        const float* gcur = gis + (t & 1) * 1600;
        float* gnxt = gis + ((t + 1) & 1) * 1600;

        // ---- stage h_prev slice (float4, coalesced LDG / conflict-free STS) ----
        if (t == 0) {
            const float4 z4 = make_float4(0.f, 0.f, 0.f, 0.f);
            for (int v = tid; v < 64 * 64; v += 256) {
                const int b = v >> 6, kq = v & 63;
                *(float4*)&hs[b * 260 + kq * 4] = z4;
            }
        } else {
#pragma unroll 4
            for (int v = tid; v < 64 * 64; v += 256) {
                const int b = v >> 6, kq = v & 63;
                *(float4*)&hs[b * 260 + kq * 4] =
                    *(const float4*)&hprev[(b0 + b) * H_ + kq * 4];
            }
        }

        // ---- prefetch gi(t+1) into registers (DRAM latency hides under GEMM) ----
        {
            const int tn = (t + 1 < T_) ? (t + 1) : t;
#pragma unroll
            for (int q = 0; q < 6; q++) {
                const size_t row = tmajor ? ((size_t)tn * B_ + b0 + gq_b[q])
                                          : ((size_t)(b0 + gq_b[q]) * T_ + tn);
                greg[q] = __ldg(&gi[row * G_ + gq_col[q]]);
            }
        }
        __syncthreads();

        // ---- warp-split-K partial GEMM: gh_partial[64][24], k in [kbase, kbase+32) ----
        float acc[8][6];
#pragma unroll
        for (int i = 0; i < 8; i++)
#pragma unroll
            for (int g = 0; g < 6; g++) acc[i][g] = 0.f;

#pragma unroll 4
        for (int kb = 0; kb < 8; kb++) {
            const int k = kbase + kb * 4;
            float4 wv[6];
#pragma unroll
            for (int g = 0; g < 6; g++)
                wv[g] = *(const float4*)&wsl[(g0l + g) * 260 + k];
#pragma unroll
            for (int i = 0; i < 8; i++) {
                const float4 hv = *(const float4*)&hs[(bl + 8 * i) * 260 + k];
#pragma unroll
                for (int g = 0; g < 6; g++) {
                    acc[i][g] += hv.x * wv[g].x;
                    acc[i][g] += hv.y * wv[g].y;
                    acc[i][g] += hv.z * wv[g].z;
                    acc[i][g] += hv.w * wv[g].w;
                }
            }
        }
#pragma unroll
        for (int i = 0; i < 8; i++) {
            float* p = &part[(w * 64 + bl + 8 * i) * 25 + g0l];
#pragma unroll
            for (int g = 0; g < 6; g++) p[g] = acc[i][g];
        }
        // stash prefetched gi into the other buffer
#pragma unroll
        for (int q = 0; q < 6; q++) gnxt[gq_sm[q]] = greg[q];
        __syncthreads();

        // ---- reduce 8 partials + gate math (all strides coprime with 32 banks) ----
#pragma unroll
        for (int p = 0; p < 2; p++) {
            const int pr = tid + p * 256;
            const int b = pr & 63, jj = pr >> 6;
            float sr = bsl[jj], sz = bsl[8 + jj], sn = bsl[16 + jj];
#pragma unroll
            for (int ww = 0; ww < 8; ww++) {
                const float* pp = &part[(ww * 64 + b) * 25];
                sr += pp[jj];
                sz += pp[8 + jj];
                sn += pp[16 + jj];
            }
            sr += gcur[b * 25 + jj];
            sz += gcur[b * 25 + 8 + jj];
            const float r = __fdividef(1.f, 1.f + __expf(-sr));
            const float z = __fdividef(1.f, 1.f + __expf(-sz));
            const float a = gcur[b * 25 + 16 + jj] + r * sn;
            const float n = __fdividef(2.f, 1.f + __expf(-2.f * a)) - 1.f;
            const float hold = hs[b * 260 + j0 + jj];
            hst[b * 9 + jj] = (1.f - z) * n + z * hold;
        }
        __syncthreads();

        // ---- writeback h_new (and layer-0 sequence output) ----
#pragma unroll
        for (int p = 0; p < 2; p++) {
            const int idx = tid + p * 256;
            const int b = idx >> 3, jj = idx & 7;
            const float v = hst[b * 9 + jj];
            hnext[(b0 + b) * H_ + j0 + jj] = v;
            if (hseq) hseq[((size_t)t * B_ + b0 + b) * H_ + j0 + jj] = v;
        }

        // ---- per-group (32 CTA) barrier, tight L2 poll ----
        __threadfence();
        __syncthreads();
        if (tid == 0) {
            const unsigned g = g_gen[grp];
            if (atomicAdd(&g_cnt[grp], 1u) == (unsigned)(GRP_CTAS - 1)) {
                g_cnt[grp] = 0;
                __threadfence();
                g_gen[grp] = g + 1u;
            } else {
                while (g_gen[grp] == g) {}
            }
            __threadfence();
        }
        __syncthreads();
    }
}

// ---------------- final FC: out[256,10] = h @ Wfc^T + bfc -------------------------
__global__ void fc_kernel(const float* __restrict__ h, const float* __restrict__ Wfc,
                          const float* __restrict__ bfc, float* __restrict__ out)
{
    const int b = blockIdx.x;
    const int lane = threadIdx.x;
    float hv[8];
#pragma unroll
    for (int i = 0; i < 8; i++) hv[i] = h[b * H_ + lane + 32 * i];
    for (int cc = 0; cc < C_; cc++) {
        float s = 0.f;
#pragma unroll
        for (int i = 0; i < 8; i++) s += hv[i] * Wfc[cc * H_ + lane + 32 * i];
#pragma unroll
        for (int o = 16; o > 0; o >>= 1) s += __shfl_down_sync(0xffffffffu, s, o);
        if (lane == 0) out[b * C_ + cc] = s + bfc[cc];
    }
}

// ---------------- launch ----------------------------------------------------------
extern "C" void kernel_launch(void* const* d_in, const int* in_sizes, int n_in,
                              void* d_out, int out_size)
{
    (void)in_sizes; (void)n_in; (void)out_size;
    const float* x    = (const float*)d_in[0];
    const float* Wih0 = (const float*)d_in[1];
    const float* Whh0 = (const float*)d_in[2];
    const float* bih0 = (const float*)d_in[3];
    const float* bhh0 = (const float*)d_in[4];
    const float* Wih1 = (const float*)d_in[5];
    const float* Whh1 = (const float*)d_in[6];
    const float* bih1 = (const float*)d_in[7];
    const float* bhh1 = (const float*)d_in[8];
    const float* Wfc  = (const float*)d_in[9];
    const float* bfc  = (const float*)d_in[10];
    float* out = (float*)d_out;

    float *p_gi, *p_h1, *p_hb;
    cudaGetSymbolAddress((void**)&p_gi, g_gi);
    cudaGetSymbolAddress((void**)&p_h1, g_h1);
    cudaGetSymbolAddress((void**)&p_hb, g_hbuf);

    const int scan_smem = 39488 * 4;
    cudaFuncSetAttribute(gru_scan, cudaFuncAttributeMaxDynamicSharedMemorySize, scan_smem);

    const dim3 gg(1024, 6);  // M/128 = 131072/128, N/128 = 768/128

    // layer 0: gi0 = x @ Wih0^T + bih0   (gi layout [B][T][768])
    gemm_nt<<<gg, 256>>>(x, Wih0, bih0, p_gi, D_);
    gru_scan<<<NCTA_SCAN, 256, scan_smem>>>(p_gi, Whh0, bhh0, p_h1, /*tmajor=*/0);

    // layer 1: gi1 = h1 @ Wih1^T + bih1  (h1 and gi1 in [T][B][*] layout)
    gemm_nt<<<gg, 256>>>(p_h1, Wih1, bih1, p_gi, H_);
    gru_scan<<<NCTA_SCAN, 256, scan_smem>>>(p_gi, Whh1, bhh1, nullptr, /*tmajor=*/1);

    // classifier on final hidden state (in g_hbuf[0] after 512 steps)
    fc_kernel<<<B_, 32>>>(p_hb, Wfc, bfc, out);
}